// round 2
// baseline (speedup 1.0000x reference)
#include <cuda_runtime.h>

#define BDIM  4
#define TDIM  2048
#define CDIM  1024
#define NHEAD 16
#define HDIM  64
#define NTOK  (BDIM*TDIM)   // 8192

// ---------------- scratch (static device allocations; no cudaMalloc) ----------------
__device__ float g_Q[(size_t)NTOK * CDIM];   // [B,H,T,d]
__device__ float g_K[(size_t)NTOK * CDIM];   // [B,H,T,d]
__device__ float g_V[(size_t)NTOK * CDIM];   // [B,H,T,d]
__device__ float g_A[(size_t)NTOK * CDIM];   // attention out, [B,T,C]

// =====================================================================================
// GEMM: C[n,m] = sum_k A[n,k] * W[m,k] + bias[m]
//   A: [8192,1024] row-major, W: [1024,1024] row-major (Linear weight, so x @ W^T)
//   SPLIT=1: write head-split layout [B,H,T,d];  SPLIT=0: plain [N,M] row-major.
// 128x128 block tile, BK=16, 256 threads, 8x8 micro-tile (split halves for
// conflict-free LDS.128).
// =====================================================================================
template<int SPLIT>
__global__ __launch_bounds__(256) void gemm128(const float* __restrict__ A,
                                               const float* __restrict__ W,
                                               const float* __restrict__ bias,
                                               float* __restrict__ C) {
    __shared__ float As[16 * 132];   // k-major transposed: As[kk*132 + row]
    __shared__ float Ws[16 * 132];

    const int tid = threadIdx.x;
    const int tx = tid & 15;          // 0..15
    const int ty = tid >> 4;          // 0..15
    const int n0 = blockIdx.y << 7;
    const int m0 = blockIdx.x << 7;

    float acc[8][8];
#pragma unroll
    for (int i = 0; i < 8; i++)
#pragma unroll
        for (int j = 0; j < 8; j++) acc[i][j] = 0.0f;

    const int lc = tid & 15;   // k within k-tile
    const int lr = tid >> 4;   // row base

    for (int k0 = 0; k0 < CDIM; k0 += 16) {
#pragma unroll
        for (int i = 0; i < 8; i++) {
            const int r = lr + (i << 4);
            As[lc * 132 + r] = A[(size_t)(n0 + r) * CDIM + k0 + lc];
            Ws[lc * 132 + r] = W[(size_t)(m0 + r) * CDIM + k0 + lc];
        }
        __syncthreads();
#pragma unroll
        for (int kk = 0; kk < 16; kk++) {
            const float4 a0 = *(const float4*)&As[kk * 132 + (ty << 2)];
            const float4 a1 = *(const float4*)&As[kk * 132 + 64 + (ty << 2)];
            const float4 w0 = *(const float4*)&Ws[kk * 132 + (tx << 2)];
            const float4 w1 = *(const float4*)&Ws[kk * 132 + 64 + (tx << 2)];
            const float av[8] = {a0.x, a0.y, a0.z, a0.w, a1.x, a1.y, a1.z, a1.w};
            const float wv[8] = {w0.x, w0.y, w0.z, w0.w, w1.x, w1.y, w1.z, w1.w};
#pragma unroll
            for (int i = 0; i < 8; i++)
#pragma unroll
                for (int j = 0; j < 8; j++)
                    acc[i][j] = fmaf(av[i], wv[j], acc[i][j]);
        }
        __syncthreads();
    }

#pragma unroll
    for (int i = 0; i < 8; i++) {
        const int n = n0 + ((i < 4) ? (ty << 2) + i : 64 + (ty << 2) + i - 4);
#pragma unroll
        for (int j = 0; j < 8; j++) {
            const int m = m0 + ((j < 4) ? (tx << 2) + j : 64 + (tx << 2) + j - 4);
            const float v = acc[i][j] + bias[m];
            if (SPLIT) {
                const int bb = n >> 11;      // n / T
                const int t  = n & 2047;
                const int h  = m >> 6;       // m / HDIM
                const int dd = m & 63;
                g_dummy_noop:;
                C[(((size_t)bb * NHEAD + h) * TDIM + t) * HDIM + dd] = v;
            } else {
                C[(size_t)n * CDIM + m] = v;
            }
        }
    }
}

// =====================================================================================
// Flash attention: one block per (batch*head, 64-query tile). BLOCK_M=BLOCK_N=64.
// Q,K,V in [B,H,T,d]. Output written directly to [B,T,C] layout (head-merged).
// S stored transposed in smem: Sts[c][r] (stride 65) so softmax row-scan and the
// P.V broadcast reads are bank-conflict free.
// =====================================================================================
__global__ __launch_bounds__(256) void attn64(const float* __restrict__ Q,
                                              const float* __restrict__ K,
                                              const float* __restrict__ V,
                                              float* __restrict__ O) {
    extern __shared__ float sm[];
    float* Qts = sm;                  // [64][64] k-major: Qts[k*64 + r]
    float* Kts = sm + 4096;           // [64][64] k-major: Kts[k*64 + c]
    float* Vs  = sm + 8192;           // [64][64] row-major: Vs[c*64 + j]
    float* Sts = sm + 12288;          // [64][65]: Sts[c*65 + r]
    float* rAlpha = sm + 12288 + 4160;   // [64]
    float* rLinv  = rAlpha + 64;         // [64]

    const int tid = threadIdx.x;
    const int tx = tid & 15;
    const int ty = tid >> 4;
    const int bh = blockIdx.y;           // b*NHEAD + h
    const int q0 = blockIdx.x << 6;

    const float* Qg = Q + ((size_t)bh * TDIM + q0) * HDIM;
    const float* Kg = K + (size_t)bh * TDIM * HDIM;
    const float* Vg = V + (size_t)bh * TDIM * HDIM;

    // ---- load Q tile transposed (once) ----
    {
        const int k0 = (tid & 15) << 2;
#pragma unroll
        for (int it = 0; it < 4; it++) {
            const int r = (tid >> 4) + (it << 4);
            const float4 q4 = *(const float4*)&Qg[(size_t)r * HDIM + k0];
            Qts[(k0 + 0) * 64 + r] = q4.x;
            Qts[(k0 + 1) * 64 + r] = q4.y;
            Qts[(k0 + 2) * 64 + r] = q4.z;
            Qts[(k0 + 3) * 64 + r] = q4.w;
        }
    }

    float o[4][4];
#pragma unroll
    for (int i = 0; i < 4; i++)
#pragma unroll
        for (int j = 0; j < 4; j++) o[i][j] = 0.0f;

    float m_r = -1e30f;   // only meaningful for tid < 64
    float l_r = 0.0f;

    for (int kt = 0; kt < TDIM / 64; kt++) {
        __syncthreads();   // previous iteration done reading Vs/Sts
        // ---- load K tile transposed + V tile ----
        {
            const int k0 = (tid & 15) << 2;
            const float* Kt = Kg + (size_t)(kt << 6) * HDIM;
#pragma unroll
            for (int it = 0; it < 4; it++) {
                const int c = (tid >> 4) + (it << 4);
                const float4 k4 = *(const float4*)&Kt[(size_t)c * HDIM + k0];
                Kts[(k0 + 0) * 64 + c] = k4.x;
                Kts[(k0 + 1) * 64 + c] = k4.y;
                Kts[(k0 + 2) * 64 + c] = k4.z;
                Kts[(k0 + 3) * 64 + c] = k4.w;
            }
            const float* Vt = Vg + (size_t)(kt << 6) * HDIM;
#pragma unroll
            for (int it = 0; it < 4; it++) {
                const int idx = (tid + (it << 8)) << 2;   // 0..4092
                *(float4*)&Vs[idx] = *(const float4*)&Vt[idx];
            }
        }
        __syncthreads();

        // ---- S = (K . Q^T) * scale, stored Sts[c][r] ----
        {
            float s[4][4];
#pragma unroll
            for (int i = 0; i < 4; i++)
#pragma unroll
                for (int j = 0; j < 4; j++) s[i][j] = 0.0f;
#pragma unroll 8
            for (int k = 0; k < 64; k++) {
                const float4 kv = *(const float4*)&Kts[k * 64 + (ty << 2)];
                const float4 qv = *(const float4*)&Qts[k * 64 + (tx << 2)];
                const float kc[4] = {kv.x, kv.y, kv.z, kv.w};
                const float qr[4] = {qv.x, qv.y, qv.z, qv.w};
#pragma unroll
                for (int i = 0; i < 4; i++)
#pragma unroll
                    for (int j = 0; j < 4; j++)
                        s[i][j] = fmaf(kc[i], qr[j], s[i][j]);
            }
#pragma unroll
            for (int i = 0; i < 4; i++)
#pragma unroll
                for (int j = 0; j < 4; j++)
                    Sts[((ty << 2) + i) * 65 + (tx << 2) + j] = s[i][j] * 0.125f;
        }
        __syncthreads();

        // ---- online softmax (one thread per query row) ----
        if (tid < 64) {
            const int r = tid;
            float mx = m_r;
#pragma unroll 8
            for (int c = 0; c < 64; c++) mx = fmaxf(mx, Sts[c * 65 + r]);
            const float alpha = __expf(m_r - mx);
            float sum = 0.0f;
#pragma unroll 8
            for (int c = 0; c < 64; c++) {
                const float p = __expf(Sts[c * 65 + r] - mx);
                Sts[c * 65 + r] = p;
                sum += p;
            }
            l_r = l_r * alpha + sum;
            m_r = mx;
            rAlpha[r] = alpha;
        }
        __syncthreads();

        // ---- O = O*alpha + P . V ----
        {
            float al[4];
#pragma unroll
            for (int i = 0; i < 4; i++) al[i] = rAlpha[(ty << 2) + i];
#pragma unroll
            for (int i = 0; i < 4; i++)
#pragma unroll
                for (int j = 0; j < 4; j++) o[i][j] *= al[i];
#pragma unroll 8
            for (int c = 0; c < 64; c++) {
                const float4 vv = *(const float4*)&Vs[c * 64 + (tx << 2)];
                const float vj[4] = {vv.x, vv.y, vv.z, vv.w};
                float p[4];
#pragma unroll
                for (int i = 0; i < 4; i++) p[i] = Sts[c * 65 + (ty << 2) + i];
#pragma unroll
                for (int i = 0; i < 4; i++)
#pragma unroll
                    for (int j = 0; j < 4; j++)
                        o[i][j] = fmaf(p[i], vj[j], o[i][j]);
            }
        }
    }

    __syncthreads();
    if (tid < 64) rLinv[tid] = 1.0f / l_r;
    __syncthreads();

    // ---- write out to [B, T, C] with head-merged columns ----
    {
        const int b = bh >> 4;
        const int h = bh & 15;
#pragma unroll
        for (int i = 0; i < 4; i++) {
            const float inv = rLinv[(ty << 2) + i];
            float4 ov;
            ov.x = o[i][0] * inv;
            ov.y = o[i][1] * inv;
            ov.z = o[i][2] * inv;
            ov.w = o[i][3] * inv;
            const size_t n = (size_t)b * TDIM + q0 + (ty << 2) + i;
            *(float4*)&O[n * CDIM + h * HDIM + (tx << 2)] = ov;
        }
    }
}

// =====================================================================================
extern "C" void kernel_launch(void* const* d_in, const int* in_sizes, int n_in,
                              void* d_out, int out_size) {
    const float* x  = (const float*)d_in[0];
    const float* Wq = (const float*)d_in[1];
    const float* bq = (const float*)d_in[2];
    const float* Wk = (const float*)d_in[3];
    const float* bk = (const float*)d_in[4];
    const float* Wv = (const float*)d_in[5];
    const float* bv = (const float*)d_in[6];
    const float* Wp = (const float*)d_in[7];
    const float* bp = (const float*)d_in[8];
    float* out = (float*)d_out;

    float *Qp, *Kp, *Vp, *Ap;
    cudaGetSymbolAddress((void**)&Qp, g_Q);
    cudaGetSymbolAddress((void**)&Kp, g_K);
    cudaGetSymbolAddress((void**)&Vp, g_V);
    cudaGetSymbolAddress((void**)&Ap, g_A);

    const dim3 gg(CDIM / 128, NTOK / 128);   // (8, 64)

    gemm128<1><<<gg, 256>>>(x, Wq, bq, Qp);
    gemm128<1><<<gg, 256>>>(x, Wk, bk, Kp);
    gemm128<1><<<gg, 256>>>(x, Wv, bv, Vp);

    const int smem_bytes = (4096 * 3 + 64 * 65 + 128) * (int)sizeof(float);  // 66816 B
    cudaFuncSetAttribute(attn64, cudaFuncAttributeMaxDynamicSharedMemorySize, smem_bytes);
    const dim3 ga(TDIM / 64, BDIM * NHEAD);  // (32, 64)
    attn64<<<ga, 256, smem_bytes>>>(Qp, Kp, Vp, Ap);

    gemm128<0><<<gg, 256>>>(Ap, Wp, bp, out);
}

// round 4
// speedup vs baseline: 1.1723x; 1.1723x over previous
#include <cuda_runtime.h>
#include <cstdint>

#define BDIM  4
#define TDIM  2048
#define CDIM  1024
#define NHEAD 16
#define HDIM  64
#define NTOK  (BDIM*TDIM)   // 8192

// ---------------- scratch (static device arrays; no cudaMalloc) ----------------
__device__ __align__(1024) float g_Q[(size_t)NTOK * CDIM];   // [B,H,T,d]
__device__ __align__(1024) float g_K[(size_t)NTOK * CDIM];   // [B,H,T,d]
__device__ __align__(1024) float g_V[(size_t)NTOK * CDIM];   // [B,H,T,d]
__device__ __align__(1024) float g_A[(size_t)NTOK * CDIM];   // attention out [B,T,C]

// ---------------- helpers ----------------
__device__ __forceinline__ uint32_t s2u(const void* p) {
    uint32_t a;
    asm("{ .reg .u64 t; cvta.to.shared.u64 t, %1; cvt.u32.u64 %0, t; }" : "=r"(a) : "l"(p));
    return a;
}
__device__ __forceinline__ void cpasync16(uint32_t dst, const float* src) {
    asm volatile("cp.async.cg.shared.global [%0], [%1], 16;" :: "r"(dst), "l"(src) : "memory");
}
#define CP_COMMIT() asm volatile("cp.async.commit_group;" ::: "memory")
#define CP_WAIT1()  asm volatile("cp.async.wait_group 1;" ::: "memory")

// split fp32 into hi (rn-tf32) + lo (rn-tf32 of remainder); hi+lo ~ 21-bit accurate
__device__ __forceinline__ void split_tf32(float v, uint32_t& hi, uint32_t& lo) {
    uint32_t h;
    asm("cvt.rn.tf32.f32 %0, %1;" : "=r"(h) : "f"(v));
    const float lf = v - __uint_as_float(h);
    uint32_t l;
    asm("cvt.rn.tf32.f32 %0, %1;" : "=r"(l) : "f"(lf));
    hi = h; lo = l;
}

// D += A(16x8,row) * B(8x8,col) in tf32, fp32 accumulate
__device__ __forceinline__ void mma_16n8k8(float* c, const uint32_t* a, const uint32_t* b) {
    asm volatile(
        "mma.sync.aligned.m16n8k8.row.col.f32.tf32.tf32.f32 "
        "{%0,%1,%2,%3}, {%4,%5,%6,%7}, {%8,%9}, {%0,%1,%2,%3};"
        : "+f"(c[0]), "+f"(c[1]), "+f"(c[2]), "+f"(c[3])
        : "r"(a[0]), "r"(a[1]), "r"(a[2]), "r"(a[3]), "r"(b[0]), "r"(b[1]));
}

// =====================================================================================
// GEMM: C[n,m] = sum_k A[n,k]*W[m,k] + bias[m]   (A:[8192,1024], W:[1024,1024], both k-major)
// mma.sync tf32 x3 compensation. BM=128, BN=128, BK=32, 256 threads (8 warps, 2x4 grid,
// warp tile 64x32). cp.async double-buffered raw-fp32 smem tiles (stride 36 floats).
// SPLIT=1 -> write [B,H,T,d]; SPLIT=0 -> [N,M] row-major.
// =====================================================================================
#define GK_STRIDE 36
#define GK_STAGEF (2 * 128 * GK_STRIDE)          // floats per stage (A tile + W tile)
#define GK_SMEM   (2 * GK_STAGEF * 4)            // 73728 bytes

template<int SPLIT>
__global__ __launch_bounds__(256) void gemm_mma(const float* __restrict__ A,
                                                const float* __restrict__ W,
                                                const float* __restrict__ bias,
                                                float* __restrict__ C) {
    extern __shared__ __align__(16) float sm[];
    const uint32_t sb = s2u(sm);

    const int tid  = threadIdx.x;
    const int lane = tid & 31;
    const int g = lane >> 2, t = lane & 3;
    const int wid = tid >> 5;
    const int wm = wid & 1;        // 0..1  -> 64-row slab
    const int wn = wid >> 1;       // 0..3  -> 32-col slab
    const int n0 = blockIdx.x << 7;   // feature tile
    const int m0 = blockIdx.y << 7;   // token tile

    float acc[4][4][4];
#pragma unroll
    for (int i = 0; i < 4; i++)
#pragma unroll
        for (int j = 0; j < 4; j++)
#pragma unroll
            for (int q = 0; q < 4; q++) acc[i][j][q] = 0.0f;

    // issue cp.async for chunk c into stage stg
    auto issue = [&](int c, int stg) {
        const float* Ag = A + (size_t)m0 * CDIM + c * 32;
        const float* Wg = W + (size_t)n0 * CDIM + c * 32;
        const uint32_t sA = sb + (uint32_t)stg * GK_STAGEF * 4;
        const uint32_t sW = sA + 128 * GK_STRIDE * 4;
#pragma unroll
        for (int j = 0; j < 4; j++) {
            const int f = tid + (j << 8);        // 0..1023 float4 slots
            const int row = f >> 3, q = f & 7;   // 128 rows x 8 float4
            const uint32_t off = (uint32_t)(row * GK_STRIDE + (q << 2)) * 4;
            cpasync16(sA + off, Ag + (size_t)row * CDIM + (q << 2));
            cpasync16(sW + off, Wg + (size_t)row * CDIM + (q << 2));
        }
    };

    issue(0, 0);
    CP_COMMIT();

    for (int c = 0; c < 32; c++) {
        if (c + 1 < 32) issue(c + 1, (c + 1) & 1);
        CP_COMMIT();
        CP_WAIT1();
        __syncthreads();

        const float* Ab = sm + (c & 1) * GK_STAGEF;
        const float* Wb = Ab + 128 * GK_STRIDE;

#pragma unroll
        for (int ks = 0; ks < 4; ks++) {
            const int k0 = ks << 3;
            uint32_t ah[4][4], al[4][4];
#pragma unroll
            for (int mf = 0; mf < 4; mf++) {
                const int r0 = wm * 64 + mf * 16 + g;
                split_tf32(Ab[r0 * GK_STRIDE + k0 + t],           ah[mf][0], al[mf][0]);
                split_tf32(Ab[(r0 + 8) * GK_STRIDE + k0 + t],     ah[mf][1], al[mf][1]);
                split_tf32(Ab[r0 * GK_STRIDE + k0 + t + 4],       ah[mf][2], al[mf][2]);
                split_tf32(Ab[(r0 + 8) * GK_STRIDE + k0 + t + 4], ah[mf][3], al[mf][3]);
            }
            uint32_t bh[4][2], bl[4][2];
#pragma unroll
            for (int nf = 0; nf < 4; nf++) {
                const int c0 = wn * 32 + nf * 8 + g;
                split_tf32(Wb[c0 * GK_STRIDE + k0 + t],     bh[nf][0], bl[nf][0]);
                split_tf32(Wb[c0 * GK_STRIDE + k0 + t + 4], bh[nf][1], bl[nf][1]);
            }
#pragma unroll
            for (int mf = 0; mf < 4; mf++)
#pragma unroll
                for (int nf = 0; nf < 4; nf++) {
                    mma_16n8k8(acc[mf][nf], ah[mf], bh[nf]);
                    mma_16n8k8(acc[mf][nf], ah[mf], bl[nf]);
                    mma_16n8k8(acc[mf][nf], al[mf], bh[nf]);
                }
        }
        __syncthreads();
    }

    // -------- epilogue --------
#pragma unroll
    for (int nf = 0; nf < 4; nf++) {
        const int col = n0 + wn * 32 + nf * 8 + 2 * t;
        const float2 bv = *(const float2*)&bias[col];
#pragma unroll
        for (int mf = 0; mf < 4; mf++) {
            const int r0 = m0 + wm * 64 + mf * 16 + g;
            float2 v0, v1;
            v0.x = acc[mf][nf][0] + bv.x;  v0.y = acc[mf][nf][1] + bv.y;
            v1.x = acc[mf][nf][2] + bv.x;  v1.y = acc[mf][nf][3] + bv.y;
            if (SPLIT) {
                const int h = col >> 6, d = col & 63;
                const int b0 = r0 >> 11, t0 = r0 & 2047;
                *(float2*)&C[(((size_t)b0 * NHEAD + h) * TDIM + t0) * HDIM + d] = v0;
                const int r1 = r0 + 8;
                const int b1 = r1 >> 11, t1 = r1 & 2047;
                *(float2*)&C[(((size_t)b1 * NHEAD + h) * TDIM + t1) * HDIM + d] = v1;
            } else {
                *(float2*)&C[(size_t)r0 * CDIM + col] = v0;
                *(float2*)&C[(size_t)(r0 + 8) * CDIM + col] = v1;
            }
        }
    }
}

// =====================================================================================
// Flash attention (SIMT fp32) — identical to the R1 kernel that passed at 1.4e-6.
// =====================================================================================
__global__ __launch_bounds__(256) void attn64(const float* __restrict__ Q,
                                              const float* __restrict__ K,
                                              const float* __restrict__ V,
                                              float* __restrict__ O) {
    extern __shared__ float sma[];
    float* Qts = sma;
    float* Kts = sma + 4096;
    float* Vs  = sma + 8192;
    float* Sts = sma + 12288;
    float* rAlpha = sma + 12288 + 4160;
    float* rLinv  = rAlpha + 64;

    const int tid = threadIdx.x;
    const int tx = tid & 15;
    const int ty = tid >> 4;
    const int bh = blockIdx.y;
    const int q0 = blockIdx.x << 6;

    const float* Qg = Q + ((size_t)bh * TDIM + q0) * HDIM;
    const float* Kg = K + (size_t)bh * TDIM * HDIM;
    const float* Vg = V + (size_t)bh * TDIM * HDIM;

    {
        const int k0 = (tid & 15) << 2;
#pragma unroll
        for (int it = 0; it < 4; it++) {
            const int r = (tid >> 4) + (it << 4);
            const float4 q4 = *(const float4*)&Qg[(size_t)r * HDIM + k0];
            Qts[(k0 + 0) * 64 + r] = q4.x;
            Qts[(k0 + 1) * 64 + r] = q4.y;
            Qts[(k0 + 2) * 64 + r] = q4.z;
            Qts[(k0 + 3) * 64 + r] = q4.w;
        }
    }

    float o[4][4];
#pragma unroll
    for (int i = 0; i < 4; i++)
#pragma unroll
        for (int j = 0; j < 4; j++) o[i][j] = 0.0f;

    float m_r = -1e30f;
    float l_r = 0.0f;

    for (int kt = 0; kt < TDIM / 64; kt++) {
        __syncthreads();
        {
            const int k0 = (tid & 15) << 2;
            const float* Kt = Kg + (size_t)(kt << 6) * HDIM;
#pragma unroll
            for (int it = 0; it < 4; it++) {
                const int c = (tid >> 4) + (it << 4);
                const float4 k4 = *(const float4*)&Kt[(size_t)c * HDIM + k0];
                Kts[(k0 + 0) * 64 + c] = k4.x;
                Kts[(k0 + 1) * 64 + c] = k4.y;
                Kts[(k0 + 2) * 64 + c] = k4.z;
                Kts[(k0 + 3) * 64 + c] = k4.w;
            }
            const float* Vt = Vg + (size_t)(kt << 6) * HDIM;
#pragma unroll
            for (int it = 0; it < 4; it++) {
                const int idx = (tid + (it << 8)) << 2;
                *(float4*)&Vs[idx] = *(const float4*)&Vt[idx];
            }
        }
        __syncthreads();

        {
            float s[4][4];
#pragma unroll
            for (int i = 0; i < 4; i++)
#pragma unroll
                for (int j = 0; j < 4; j++) s[i][j] = 0.0f;
#pragma unroll 8
            for (int k = 0; k < 64; k++) {
                const float4 kv = *(const float4*)&Kts[k * 64 + (ty << 2)];
                const float4 qv = *(const float4*)&Qts[k * 64 + (tx << 2)];
                const float kc[4] = {kv.x, kv.y, kv.z, kv.w};
                const float qr[4] = {qv.x, qv.y, qv.z, qv.w};
#pragma unroll
                for (int i = 0; i < 4; i++)
#pragma unroll
                    for (int j = 0; j < 4; j++)
                        s[i][j] = fmaf(kc[i], qr[j], s[i][j]);
            }
#pragma unroll
            for (int i = 0; i < 4; i++)
#pragma unroll
                for (int j = 0; j < 4; j++)
                    Sts[((ty << 2) + i) * 65 + (tx << 2) + j] = s[i][j] * 0.125f;
        }
        __syncthreads();

        if (tid < 64) {
            const int r = tid;
            float mx = m_r;
#pragma unroll 8
            for (int c = 0; c < 64; c++) mx = fmaxf(mx, Sts[c * 65 + r]);
            const float alpha = __expf(m_r - mx);
            float sum = 0.0f;
#pragma unroll 8
            for (int c = 0; c < 64; c++) {
                const float p = __expf(Sts[c * 65 + r] - mx);
                Sts[c * 65 + r] = p;
                sum += p;
            }
            l_r = l_r * alpha + sum;
            m_r = mx;
            rAlpha[r] = alpha;
        }
        __syncthreads();

        {
            float al[4];
#pragma unroll
            for (int i = 0; i < 4; i++) al[i] = rAlpha[(ty << 2) + i];
#pragma unroll
            for (int i = 0; i < 4; i++)
#pragma unroll
                for (int j = 0; j < 4; j++) o[i][j] *= al[i];
#pragma unroll 8
            for (int c = 0; c < 64; c++) {
                const float4 vv = *(const float4*)&Vs[c * 64 + (tx << 2)];
                const float vj[4] = {vv.x, vv.y, vv.z, vv.w};
                float p[4];
#pragma unroll
                for (int i = 0; i < 4; i++) p[i] = Sts[c * 65 + (ty << 2) + i];
#pragma unroll
                for (int i = 0; i < 4; i++)
#pragma unroll
                    for (int j = 0; j < 4; j++)
                        o[i][j] = fmaf(p[i], vj[j], o[i][j]);
            }
        }
    }

    __syncthreads();
    if (tid < 64) rLinv[tid] = 1.0f / l_r;
    __syncthreads();

    {
        const int b = bh >> 4;
        const int h = bh & 15;
#pragma unroll
        for (int i = 0; i < 4; i++) {
            const float inv = rLinv[(ty << 2) + i];
            float4 ov;
            ov.x = o[i][0] * inv;
            ov.y = o[i][1] * inv;
            ov.z = o[i][2] * inv;
            ov.w = o[i][3] * inv;
            const size_t n = (size_t)b * TDIM + q0 + (ty << 2) + i;
            *(float4*)&O[n * CDIM + h * HDIM + (tx << 2)] = ov;
        }
    }
}

// =====================================================================================
extern "C" void kernel_launch(void* const* d_in, const int* in_sizes, int n_in,
                              void* d_out, int out_size) {
    const float* x  = (const float*)d_in[0];
    const float* Wq = (const float*)d_in[1];
    const float* bq = (const float*)d_in[2];
    const float* Wk = (const float*)d_in[3];
    const float* bk = (const float*)d_in[4];
    const float* Wv = (const float*)d_in[5];
    const float* bv = (const float*)d_in[6];
    const float* Wp = (const float*)d_in[7];
    const float* bp = (const float*)d_in[8];
    float* out = (float*)d_out;

    float *Qp, *Kp, *Vp, *Ap;
    cudaGetSymbolAddress((void**)&Qp, g_Q);
    cudaGetSymbolAddress((void**)&Kp, g_K);
    cudaGetSymbolAddress((void**)&Vp, g_V);
    cudaGetSymbolAddress((void**)&Ap, g_A);

    cudaFuncSetAttribute(gemm_mma<1>, cudaFuncAttributeMaxDynamicSharedMemorySize, GK_SMEM);
    cudaFuncSetAttribute(gemm_mma<0>, cudaFuncAttributeMaxDynamicSharedMemorySize, GK_SMEM);

    const dim3 gg(CDIM / 128, NTOK / 128);   // (8, 64)

    gemm_mma<1><<<gg, 256, GK_SMEM>>>(x, Wq, bq, Qp);
    gemm_mma<1><<<gg, 256, GK_SMEM>>>(x, Wk, bk, Kp);
    gemm_mma<1><<<gg, 256, GK_SMEM>>>(x, Wv, bv, Vp);

    const int smem_attn = (4096 * 3 + 64 * 65 + 128) * (int)sizeof(float);  // 66816
    cudaFuncSetAttribute(attn64, cudaFuncAttributeMaxDynamicSharedMemorySize, smem_attn);
    const dim3 ga(TDIM / 64, BDIM * NHEAD);  // (32, 64)
    attn64<<<ga, 256, smem_attn>>>(Qp, Kp, Vp, Ap);

    gemm_mma<0><<<gg, 256, GK_SMEM>>>(Ap, Wp, bp, out);
}

// round 5
// speedup vs baseline: 2.2574x; 1.9257x over previous
#include <cuda_runtime.h>
#include <cuda_bf16.h>
#include <cstdint>

#define BDIM  4
#define TDIM  2048
#define CDIM  1024
#define NHEAD 16
#define HDIM  64
#define NTOK  (BDIM*TDIM)   // 8192

// ---------------- scratch (static device arrays; no cudaMalloc) ----------------
__device__ __align__(1024) float g_Q[(size_t)NTOK * CDIM];   // [B,H,T,d]
__device__ __align__(1024) float g_K[(size_t)NTOK * CDIM];   // [B,H,T,d]
__device__ __align__(1024) float g_V[(size_t)NTOK * CDIM];   // [B,H,T,d]
__device__ __align__(1024) float g_A[(size_t)NTOK * CDIM];   // attention out [B,T,C]

// ---------------- helpers ----------------
__device__ __forceinline__ void cpasync16(uint32_t dst, const float* src) {
    asm volatile("cp.async.cg.shared.global [%0], [%1], 16;" :: "r"(dst), "l"(src) : "memory");
}
__device__ __forceinline__ uint32_t s2u(const void* p) {
    uint32_t a;
    asm("{ .reg .u64 t; cvta.to.shared.u64 t, %1; cvt.u32.u64 %0, t; }" : "=r"(a) : "l"(p));
    return a;
}
#define CP_COMMIT() asm volatile("cp.async.commit_group;" ::: "memory")
#define CP_WAIT1()  asm volatile("cp.async.wait_group 1;" ::: "memory")

__device__ __forceinline__ void split_tf32(float v, uint32_t& hi, uint32_t& lo) {
    uint32_t h;
    asm("cvt.rn.tf32.f32 %0, %1;" : "=r"(h) : "f"(v));
    const float lf = v - __uint_as_float(h);
    uint32_t l;
    asm("cvt.rn.tf32.f32 %0, %1;" : "=r"(l) : "f"(lf));
    hi = h; lo = l;
}
__device__ __forceinline__ void mma_16n8k8(float* c, const uint32_t* a, const uint32_t* b) {
    asm volatile(
        "mma.sync.aligned.m16n8k8.row.col.f32.tf32.tf32.f32 "
        "{%0,%1,%2,%3}, {%4,%5,%6,%7}, {%8,%9}, {%0,%1,%2,%3};"
        : "+f"(c[0]), "+f"(c[1]), "+f"(c[2]), "+f"(c[3])
        : "r"(a[0]), "r"(a[1]), "r"(a[2]), "r"(a[3]), "r"(b[0]), "r"(b[1]));
}
// bf16 m16n8k16: D(16x8) += A(16x16 row) * B(16x8 col), fp32 accum
__device__ __forceinline__ void mma_bf16(float* c, const uint32_t* a, uint32_t b0, uint32_t b1) {
    asm volatile(
        "mma.sync.aligned.m16n8k16.row.col.f32.bf16.bf16.f32 "
        "{%0,%1,%2,%3}, {%4,%5,%6,%7}, {%8,%9}, {%0,%1,%2,%3};"
        : "+f"(c[0]), "+f"(c[1]), "+f"(c[2]), "+f"(c[3])
        : "r"(a[0]), "r"(a[1]), "r"(a[2]), "r"(a[3]), "r"(b0), "r"(b1));
}
// pack (x,y) -> bf16x2 hi (x in low half) and bf16x2 lo (the rounding remainders)
__device__ __forceinline__ void packsplit(float x, float y, uint32_t& hi, uint32_t& lo) {
    uint32_t h;
    asm("cvt.rn.bf16x2.f32 %0, %1, %2;" : "=r"(h) : "f"(y), "f"(x));   // low16 = x
    const float hx = __uint_as_float(h << 16);
    const float hy = __uint_as_float(h & 0xffff0000u);
    uint32_t l;
    asm("cvt.rn.bf16x2.f32 %0, %1, %2;" : "=r"(l) : "f"(y - hy), "f"(x - hx));
    hi = h; lo = l;
}

// =====================================================================================
// GEMM (unchanged from R4): mma.sync tf32 x3, BM=128 BN=128 BK=32, 256 thr, cp.async.
// =====================================================================================
#define GK_STRIDE 36
#define GK_STAGEF (2 * 128 * GK_STRIDE)
#define GK_SMEM   (2 * GK_STAGEF * 4)

template<int SPLIT>
__global__ __launch_bounds__(256) void gemm_mma(const float* __restrict__ A,
                                                const float* __restrict__ W,
                                                const float* __restrict__ bias,
                                                float* __restrict__ C) {
    extern __shared__ __align__(16) float sm[];
    const uint32_t sb = s2u(sm);

    const int tid  = threadIdx.x;
    const int lane = tid & 31;
    const int g = lane >> 2, t = lane & 3;
    const int wid = tid >> 5;
    const int wm = wid & 1;
    const int wn = wid >> 1;
    const int n0 = blockIdx.x << 7;
    const int m0 = blockIdx.y << 7;

    float acc[4][4][4];
#pragma unroll
    for (int i = 0; i < 4; i++)
#pragma unroll
        for (int j = 0; j < 4; j++)
#pragma unroll
            for (int q = 0; q < 4; q++) acc[i][j][q] = 0.0f;

    auto issue = [&](int c, int stg) {
        const float* Ag = A + (size_t)m0 * CDIM + c * 32;
        const float* Wg = W + (size_t)n0 * CDIM + c * 32;
        const uint32_t sA = sb + (uint32_t)stg * GK_STAGEF * 4;
        const uint32_t sW = sA + 128 * GK_STRIDE * 4;
#pragma unroll
        for (int j = 0; j < 4; j++) {
            const int f = tid + (j << 8);
            const int row = f >> 3, q = f & 7;
            const uint32_t off = (uint32_t)(row * GK_STRIDE + (q << 2)) * 4;
            cpasync16(sA + off, Ag + (size_t)row * CDIM + (q << 2));
            cpasync16(sW + off, Wg + (size_t)row * CDIM + (q << 2));
        }
    };

    issue(0, 0);
    CP_COMMIT();

    for (int c = 0; c < 32; c++) {
        if (c + 1 < 32) issue(c + 1, (c + 1) & 1);
        CP_COMMIT();
        CP_WAIT1();
        __syncthreads();

        const float* Ab = sm + (c & 1) * GK_STAGEF;
        const float* Wb = Ab + 128 * GK_STRIDE;

#pragma unroll
        for (int ks = 0; ks < 4; ks++) {
            const int k0 = ks << 3;
            uint32_t ah[4][4], al[4][4];
#pragma unroll
            for (int mf = 0; mf < 4; mf++) {
                const int r0 = wm * 64 + mf * 16 + g;
                split_tf32(Ab[r0 * GK_STRIDE + k0 + t],           ah[mf][0], al[mf][0]);
                split_tf32(Ab[(r0 + 8) * GK_STRIDE + k0 + t],     ah[mf][1], al[mf][1]);
                split_tf32(Ab[r0 * GK_STRIDE + k0 + t + 4],       ah[mf][2], al[mf][2]);
                split_tf32(Ab[(r0 + 8) * GK_STRIDE + k0 + t + 4], ah[mf][3], al[mf][3]);
            }
            uint32_t bh[4][2], bl[4][2];
#pragma unroll
            for (int nf = 0; nf < 4; nf++) {
                const int c0 = wn * 32 + nf * 8 + g;
                split_tf32(Wb[c0 * GK_STRIDE + k0 + t],     bh[nf][0], bl[nf][0]);
                split_tf32(Wb[c0 * GK_STRIDE + k0 + t + 4], bh[nf][1], bl[nf][1]);
            }
#pragma unroll
            for (int mf = 0; mf < 4; mf++)
#pragma unroll
                for (int nf = 0; nf < 4; nf++) {
                    mma_16n8k8(acc[mf][nf], ah[mf], bh[nf]);
                    mma_16n8k8(acc[mf][nf], ah[mf], bl[nf]);
                    mma_16n8k8(acc[mf][nf], al[mf], bh[nf]);
                }
        }
        __syncthreads();
    }

#pragma unroll
    for (int nf = 0; nf < 4; nf++) {
        const int col = n0 + wn * 32 + nf * 8 + 2 * t;
        const float2 bv = *(const float2*)&bias[col];
#pragma unroll
        for (int mf = 0; mf < 4; mf++) {
            const int r0 = m0 + wm * 64 + mf * 16 + g;
            float2 v0, v1;
            v0.x = acc[mf][nf][0] + bv.x;  v0.y = acc[mf][nf][1] + bv.y;
            v1.x = acc[mf][nf][2] + bv.x;  v1.y = acc[mf][nf][3] + bv.y;
            if (SPLIT) {
                const int h = col >> 6, d = col & 63;
                const int b0 = r0 >> 11, t0 = r0 & 2047;
                *(float2*)&C[(((size_t)b0 * NHEAD + h) * TDIM + t0) * HDIM + d] = v0;
                const int r1 = r0 + 8;
                const int b1 = r1 >> 11, t1 = r1 & 2047;
                *(float2*)&C[(((size_t)b1 * NHEAD + h) * TDIM + t1) * HDIM + d] = v1;
            } else {
                *(float2*)&C[(size_t)r0 * CDIM + col] = v0;
                *(float2*)&C[(size_t)(r0 + 8) * CDIM + col] = v1;
            }
        }
    }
}

// =====================================================================================
// Flash attention on tensor cores: bf16x2 (hi/lo split, 3-term) m16n8k16 mma.
// BM=128 queries/CTA (8 warps x m16), BN=64 keys/iter, 32 iters. Q,K,V in [B,H,T,d].
// QK: S = Qs*K^T in exp2 domain (scale*log2e folded into Q). P packs directly into
// A-fragments (C layout == A layout). PV: O += P*V with V transposed in smem.
// Output to [B,T,C].
// =====================================================================================
#define AT_STRIDE 36   // u32 per row (32 pairs + 4 pad) -> conflict-free frag access

__global__ __launch_bounds__(256) void attn_mma(const float* __restrict__ Q,
                                                const float* __restrict__ K,
                                                const float* __restrict__ V,
                                                float* __restrict__ O) {
    __shared__ uint32_t KbH[64 * AT_STRIDE];   // [key][dimpair] bf16x2 hi
    __shared__ uint32_t KbL[64 * AT_STRIDE];   // lo
    __shared__ uint32_t VtH[64 * AT_STRIDE];   // [dim][keypair] bf16x2 hi
    __shared__ uint32_t VtL[64 * AT_STRIDE];   // lo

    const int tid  = threadIdx.x;
    const int lane = tid & 31;
    const int g = lane >> 2, t = lane & 3;
    const int w = tid >> 5;
    const int bh = blockIdx.y;
    const int q0 = blockIdx.x << 7;

    const float* Qg = Q + ((size_t)bh * TDIM + q0) * HDIM;
    const float* Kg = K + (size_t)bh * TDIM * HDIM;
    const float* Vg = V + (size_t)bh * TDIM * HDIM;

    // ---- Q A-fragments, scaled by 0.125*log2(e), split hi/lo (register-resident) ----
    uint32_t qh[4][4], ql[4][4];
    {
        const float sc = 0.125f * 1.4426950408889634f;
        const int r0 = 16 * w + g, r1 = r0 + 8;
#pragma unroll
        for (int ks = 0; ks < 4; ks++) {
            const int c0 = 16 * ks + 2 * t;
            float2 v00 = *(const float2*)&Qg[(size_t)r0 * HDIM + c0];
            float2 v10 = *(const float2*)&Qg[(size_t)r1 * HDIM + c0];
            float2 v01 = *(const float2*)&Qg[(size_t)r0 * HDIM + c0 + 8];
            float2 v11 = *(const float2*)&Qg[(size_t)r1 * HDIM + c0 + 8];
            packsplit(v00.x * sc, v00.y * sc, qh[ks][0], ql[ks][0]);
            packsplit(v10.x * sc, v10.y * sc, qh[ks][1], ql[ks][1]);
            packsplit(v01.x * sc, v01.y * sc, qh[ks][2], ql[ks][2]);
            packsplit(v11.x * sc, v11.y * sc, qh[ks][3], ql[ks][3]);
        }
    }

    // convert-phase thread mappings
    const int kc_d  = tid & 31;           // K: dim pair 0..31
    const int kc_k0 = (tid >> 5) << 3;    // K: key base (8 keys)
    const int vc_kp = tid & 31;           // V: key pair 0..31
    const int vc_d0 = (tid >> 5) << 3;    // V: dim base (8 dims)

    float kreg[16], vreg[16];
    auto loadK = [&](int kt) {
        const float* base = Kg + (size_t)((kt << 6) + kc_k0) * HDIM + 2 * kc_d;
#pragma unroll
        for (int j = 0; j < 8; j++) {
            const float2 v = *(const float2*)(base + (size_t)j * HDIM);
            kreg[2 * j] = v.x; kreg[2 * j + 1] = v.y;
        }
    };
    auto loadV = [&](int kt) {
        const float* ba = Vg + (size_t)((kt << 6) + 2 * vc_kp) * HDIM + vc_d0;
#pragma unroll
        for (int q = 0; q < 2; q++) {
            const float4 a = *(const float4*)(ba + (size_t)q * HDIM);
            const float4 b = *(const float4*)(ba + (size_t)q * HDIM + 4);
            vreg[8 * q + 0] = a.x; vreg[8 * q + 1] = a.y; vreg[8 * q + 2] = a.z; vreg[8 * q + 3] = a.w;
            vreg[8 * q + 4] = b.x; vreg[8 * q + 5] = b.y; vreg[8 * q + 6] = b.z; vreg[8 * q + 7] = b.w;
        }
    };

    float o[8][4];
#pragma unroll
    for (int nf = 0; nf < 8; nf++)
#pragma unroll
        for (int q = 0; q < 4; q++) o[nf][q] = 0.0f;

    float m0 = -1e30f, m1 = -1e30f, l0 = 0.0f, l1 = 0.0f;

    loadK(0); loadV(0);

    for (int kt = 0; kt < TDIM / 64; kt++) {
        __syncthreads();   // previous compute done reading smem

        // ---- convert prefetched K/V regs into bf16x2 hi/lo smem tiles ----
#pragma unroll
        for (int j = 0; j < 8; j++) {
            uint32_t h, l;
            packsplit(kreg[2 * j], kreg[2 * j + 1], h, l);
            KbH[(kc_k0 + j) * AT_STRIDE + kc_d] = h;
            KbL[(kc_k0 + j) * AT_STRIDE + kc_d] = l;
        }
#pragma unroll
        for (int j = 0; j < 8; j++) {
            uint32_t h, l;
            packsplit(vreg[j], vreg[8 + j], h, l);   // low = key 2kp, high = key 2kp+1
            VtH[(vc_d0 + j) * AT_STRIDE + vc_kp] = h;
            VtL[(vc_d0 + j) * AT_STRIDE + vc_kp] = l;
        }
        if (kt + 1 < TDIM / 64) { loadK(kt + 1); loadV(kt + 1); }
        __syncthreads();

        // ---- S = Qs . K^T (bf16x2, 3-term) ----
        float s[8][4];
#pragma unroll
        for (int nf = 0; nf < 8; nf++)
#pragma unroll
            for (int q = 0; q < 4; q++) s[nf][q] = 0.0f;

#pragma unroll
        for (int ks = 0; ks < 4; ks++) {
#pragma unroll
            for (int nf = 0; nf < 8; nf++) {
                const int i0 = (8 * nf + g) * AT_STRIDE + 8 * ks + t;
                const uint32_t kh0 = KbH[i0], kh1 = KbH[i0 + 4];
                const uint32_t kl0 = KbL[i0], kl1 = KbL[i0 + 4];
                mma_bf16(s[nf], qh[ks], kh0, kh1);
                mma_bf16(s[nf], qh[ks], kl0, kl1);
                mma_bf16(s[nf], ql[ks], kh0, kh1);
            }
        }

        // ---- online softmax (exp2 domain), quad-wide rows ----
        float mx0 = -1e30f, mx1 = -1e30f;
#pragma unroll
        for (int nf = 0; nf < 8; nf++) {
            mx0 = fmaxf(mx0, fmaxf(s[nf][0], s[nf][1]));
            mx1 = fmaxf(mx1, fmaxf(s[nf][2], s[nf][3]));
        }
        mx0 = fmaxf(mx0, __shfl_xor_sync(0xffffffffu, mx0, 1));
        mx0 = fmaxf(mx0, __shfl_xor_sync(0xffffffffu, mx0, 2));
        mx1 = fmaxf(mx1, __shfl_xor_sync(0xffffffffu, mx1, 1));
        mx1 = fmaxf(mx1, __shfl_xor_sync(0xffffffffu, mx1, 2));

        const float mn0 = fmaxf(m0, mx0), mn1 = fmaxf(m1, mx1);
        const float a0 = exp2f(m0 - mn0), a1 = exp2f(m1 - mn1);
        m0 = mn0; m1 = mn1;

        float sum0 = 0.0f, sum1 = 0.0f;
#pragma unroll
        for (int nf = 0; nf < 8; nf++) {
            s[nf][0] = exp2f(s[nf][0] - m0);
            s[nf][1] = exp2f(s[nf][1] - m0);
            s[nf][2] = exp2f(s[nf][2] - m1);
            s[nf][3] = exp2f(s[nf][3] - m1);
            sum0 += s[nf][0] + s[nf][1];
            sum1 += s[nf][2] + s[nf][3];
        }
        sum0 += __shfl_xor_sync(0xffffffffu, sum0, 1);
        sum0 += __shfl_xor_sync(0xffffffffu, sum0, 2);
        sum1 += __shfl_xor_sync(0xffffffffu, sum1, 1);
        sum1 += __shfl_xor_sync(0xffffffffu, sum1, 2);
        l0 = l0 * a0 + sum0;
        l1 = l1 * a1 + sum1;

#pragma unroll
        for (int nf = 0; nf < 8; nf++) {
            o[nf][0] *= a0; o[nf][1] *= a0;
            o[nf][2] *= a1; o[nf][3] *= a1;
        }

        // ---- P -> A fragments (C layout == A layout: just pack+split) ----
        uint32_t pha[8], phb[8], pla[8], plb[8];
#pragma unroll
        for (int nf = 0; nf < 8; nf++) {
            packsplit(s[nf][0], s[nf][1], pha[nf], pla[nf]);
            packsplit(s[nf][2], s[nf][3], phb[nf], plb[nf]);
        }

        // ---- O += P . V ----
#pragma unroll
        for (int ks = 0; ks < 4; ks++) {
            const uint32_t ah[4] = {pha[2 * ks], phb[2 * ks], pha[2 * ks + 1], phb[2 * ks + 1]};
            const uint32_t al[4] = {pla[2 * ks], plb[2 * ks], pla[2 * ks + 1], plb[2 * ks + 1]};
#pragma unroll
            for (int nf = 0; nf < 8; nf++) {
                const int i0 = (8 * nf + g) * AT_STRIDE + 8 * ks + t;
                const uint32_t vh0 = VtH[i0], vh1 = VtH[i0 + 4];
                const uint32_t vl0 = VtL[i0], vl1 = VtL[i0 + 4];
                mma_bf16(o[nf], ah, vh0, vh1);
                mma_bf16(o[nf], ah, vl0, vl1);
                mma_bf16(o[nf], al, vh0, vh1);
            }
        }
    }

    // ---- epilogue: normalize, write [B,T,C] ----
    const float inv0 = 1.0f / l0, inv1 = 1.0f / l1;
    const int b = bh >> 4, h = bh & 15;
    const int r0 = q0 + 16 * w + g, r1 = r0 + 8;
    float* O0 = O + ((size_t)b * TDIM + r0) * CDIM + h * HDIM;
    float* O1 = O + ((size_t)b * TDIM + r1) * CDIM + h * HDIM;
#pragma unroll
    for (int nf = 0; nf < 8; nf++) {
        float2 u0, u1;
        u0.x = o[nf][0] * inv0; u0.y = o[nf][1] * inv0;
        u1.x = o[nf][2] * inv1; u1.y = o[nf][3] * inv1;
        *(float2*)&O0[8 * nf + 2 * t] = u0;
        *(float2*)&O1[8 * nf + 2 * t] = u1;
    }
}

// =====================================================================================
extern "C" void kernel_launch(void* const* d_in, const int* in_sizes, int n_in,
                              void* d_out, int out_size) {
    const float* x  = (const float*)d_in[0];
    const float* Wq = (const float*)d_in[1];
    const float* bq = (const float*)d_in[2];
    const float* Wk = (const float*)d_in[3];
    const float* bk = (const float*)d_in[4];
    const float* Wv = (const float*)d_in[5];
    const float* bv = (const float*)d_in[6];
    const float* Wp = (const float*)d_in[7];
    const float* bp = (const float*)d_in[8];
    float* out = (float*)d_out;

    float *Qp, *Kp, *Vp, *Ap;
    cudaGetSymbolAddress((void**)&Qp, g_Q);
    cudaGetSymbolAddress((void**)&Kp, g_K);
    cudaGetSymbolAddress((void**)&Vp, g_V);
    cudaGetSymbolAddress((void**)&Ap, g_A);

    cudaFuncSetAttribute(gemm_mma<1>, cudaFuncAttributeMaxDynamicSharedMemorySize, GK_SMEM);
    cudaFuncSetAttribute(gemm_mma<0>, cudaFuncAttributeMaxDynamicSharedMemorySize, GK_SMEM);

    const dim3 gg(CDIM / 128, NTOK / 128);   // (8, 64)

    gemm_mma<1><<<gg, 256, GK_SMEM>>>(x, Wq, bq, Qp);
    gemm_mma<1><<<gg, 256, GK_SMEM>>>(x, Wk, bk, Kp);
    gemm_mma<1><<<gg, 256, GK_SMEM>>>(x, Wv, bv, Vp);

    const dim3 ga(TDIM / 128, BDIM * NHEAD);  // (16, 64)
    attn_mma<<<ga, 256>>>(Qp, Kp, Vp, Ap);

    gemm_mma<0><<<gg, 256, GK_SMEM>>>(Ap, Wp, bp, out);
}

// round 6
// speedup vs baseline: 2.8225x; 1.2503x over previous
#include <cuda_runtime.h>
#include <cuda_bf16.h>
#include <cstdint>

#define BDIM  4
#define TDIM  2048
#define CDIM  1024
#define NHEAD 16
#define HDIM  64
#define NTOK  (BDIM*TDIM)   // 8192
#define KPAIRS (CDIM/2)     // 512 u32 pairs per row

// ---------------- scratch (static device arrays; no cudaMalloc) ----------------
__device__ __align__(1024) float    g_Q[(size_t)NTOK * CDIM];     // [B,H,T,d]
__device__ __align__(1024) float    g_K[(size_t)NTOK * CDIM];
__device__ __align__(1024) float    g_V[(size_t)NTOK * CDIM];
__device__ __align__(1024) uint32_t g_XH[(size_t)NTOK * KPAIRS];  // x split hi (bf16x2)
__device__ __align__(1024) uint32_t g_XL[(size_t)NTOK * KPAIRS];  // x split lo
__device__ __align__(1024) uint32_t g_WH[(size_t)4 * CDIM * KPAIRS];
__device__ __align__(1024) uint32_t g_WL[(size_t)4 * CDIM * KPAIRS];
__device__ __align__(1024) uint32_t g_AH[(size_t)NTOK * KPAIRS];  // attn out split hi
__device__ __align__(1024) uint32_t g_AL[(size_t)NTOK * KPAIRS];

// ---------------- helpers ----------------
__device__ __forceinline__ uint32_t s2u(const void* p) {
    uint32_t a;
    asm("{ .reg .u64 t; cvta.to.shared.u64 t, %1; cvt.u32.u64 %0, t; }" : "=r"(a) : "l"(p));
    return a;
}
__device__ __forceinline__ void cpasync16(uint32_t dst, const void* src) {
    asm volatile("cp.async.cg.shared.global [%0], [%1], 16;" :: "r"(dst), "l"(src) : "memory");
}
#define CP_COMMIT() asm volatile("cp.async.commit_group;" ::: "memory")
#define CP_WAIT1()  asm volatile("cp.async.wait_group 1;" ::: "memory")

// bf16 m16n8k16: D(16x8) += A(16x16 row) * B(16x8 col), fp32 accum
__device__ __forceinline__ void mma_bf16(float* c, const uint32_t* a, uint32_t b0, uint32_t b1) {
    asm volatile(
        "mma.sync.aligned.m16n8k16.row.col.f32.bf16.bf16.f32 "
        "{%0,%1,%2,%3}, {%4,%5,%6,%7}, {%8,%9}, {%0,%1,%2,%3};"
        : "+f"(c[0]), "+f"(c[1]), "+f"(c[2]), "+f"(c[3])
        : "r"(a[0]), "r"(a[1]), "r"(a[2]), "r"(a[3]), "r"(b0), "r"(b1));
}
// pack (x,y) -> bf16x2 hi (x in low half) and bf16x2 lo (rounding remainders)
__device__ __forceinline__ void packsplit(float x, float y, uint32_t& hi, uint32_t& lo) {
    uint32_t h;
    asm("cvt.rn.bf16x2.f32 %0, %1, %2;" : "=r"(h) : "f"(y), "f"(x));   // low16 = x
    const float hx = __uint_as_float(h << 16);
    const float hy = __uint_as_float(h & 0xffff0000u);
    uint32_t l;
    asm("cvt.rn.bf16x2.f32 %0, %1, %2;" : "=r"(l) : "f"(y - hy), "f"(x - hx));
    hi = h; lo = l;
}

// ---------------- prep: fp32 -> bf16x2 hi/lo pair arrays ----------------
__global__ __launch_bounds__(256) void splitpack(const float* __restrict__ in,
                                                 uint32_t* __restrict__ hi,
                                                 uint32_t* __restrict__ lo, int npair) {
    const int i = blockIdx.x * blockDim.x + threadIdx.x;
    if (i < npair) {
        const float2 v = ((const float2*)in)[i];
        uint32_t h, l;
        packsplit(v.x, v.y, h, l);
        hi[i] = h; lo[i] = l;
    }
}

// =====================================================================================
// GEMM: C[n,m] = sum_k A[n,k]*W[m,k] + bias[m], operands pre-split bf16x2 hi/lo.
// mma.sync bf16 m16n8k16, 3-term (hh+hl+lh). BM=128 BN=128 BK=32 (16 pairs),
// 256 threads (8 warps 2x4, warp tile 64x32), cp.async double-buffered.
// SPLIT=1 -> write fp32 [B,H,T,d]; SPLIT=0 -> fp32 [N,M] row-major.
// =====================================================================================
#define GB_STRIDE 20                          // u32/row: 16 used + 4 pad (conflict-free)
#define GB_ARR    (128 * GB_STRIDE)           // u32 per array (2560)
#define GB_STAGEU (4 * GB_ARR)                // Ah, Al, Wh, Wl
#define GB_SMEM   (2 * GB_STAGEU * 4)         // 81920 bytes

template<int SPLIT>
__global__ __launch_bounds__(256) void gemm_bf16(const uint32_t* __restrict__ Ah,
                                                 const uint32_t* __restrict__ Al,
                                                 const uint32_t* __restrict__ Wh,
                                                 const uint32_t* __restrict__ Wl,
                                                 const float* __restrict__ bias,
                                                 float* __restrict__ C) {
    extern __shared__ __align__(16) uint32_t smu[];
    const uint32_t sb = s2u(smu);

    const int tid  = threadIdx.x;
    const int lane = tid & 31;
    const int g = lane >> 2, t = lane & 3;
    const int wid = tid >> 5;
    const int wm = wid & 1;         // 64-row slab
    const int wn = wid >> 1;        // 32-col slab
    const int n0 = blockIdx.x << 7;
    const int m0 = blockIdx.y << 7;

    float acc[4][4][4];
#pragma unroll
    for (int i = 0; i < 4; i++)
#pragma unroll
        for (int j = 0; j < 4; j++)
#pragma unroll
            for (int q = 0; q < 4; q++) acc[i][j][q] = 0.0f;

    // copy chunk c (16 pairs starting at pair 16c) into stage stg
    auto issue = [&](int c, int stg) {
        const uint32_t base = sb + (uint32_t)stg * GB_STAGEU * 4;
        const uint32_t* srcs[4] = {
            Ah + (size_t)m0 * KPAIRS, Al + (size_t)m0 * KPAIRS,
            Wh + (size_t)n0 * KPAIRS, Wl + (size_t)n0 * KPAIRS };
#pragma unroll
        for (int ar = 0; ar < 4; ar++) {
#pragma unroll
            for (int j = 0; j < 2; j++) {
                const int f = tid + (j << 8);          // 0..511
                const int row = f >> 2, q = f & 3;     // 128 rows x 4 16B-chunks
                cpasync16(base + (uint32_t)(ar * GB_ARR + row * GB_STRIDE + (q << 2)) * 4,
                          srcs[ar] + (size_t)row * KPAIRS + c * 16 + (q << 2));
            }
        }
    };

    issue(0, 0);
    CP_COMMIT();

    for (int c = 0; c < CDIM / 32; c++) {
        if (c + 1 < CDIM / 32) issue(c + 1, (c + 1) & 1);
        CP_COMMIT();
        CP_WAIT1();
        __syncthreads();

        const uint32_t* Ahs = smu + (c & 1) * GB_STAGEU;
        const uint32_t* Als = Ahs + GB_ARR;
        const uint32_t* Whs = Als + GB_ARR;
        const uint32_t* Wls = Whs + GB_ARR;

#pragma unroll
        for (int ks = 0; ks < 2; ks++) {
            const int k0 = ks << 3;
            uint32_t ah[4][4], al[4][4];
#pragma unroll
            for (int mf = 0; mf < 4; mf++) {
                const int i0 = (wm * 64 + mf * 16 + g) * GB_STRIDE + k0 + t;
                ah[mf][0] = Ahs[i0];
                ah[mf][1] = Ahs[i0 + 8 * GB_STRIDE];
                ah[mf][2] = Ahs[i0 + 4];
                ah[mf][3] = Ahs[i0 + 8 * GB_STRIDE + 4];
                al[mf][0] = Als[i0];
                al[mf][1] = Als[i0 + 8 * GB_STRIDE];
                al[mf][2] = Als[i0 + 4];
                al[mf][3] = Als[i0 + 8 * GB_STRIDE + 4];
            }
            uint32_t bh[4][2], bl[4][2];
#pragma unroll
            for (int nf = 0; nf < 4; nf++) {
                const int i0 = (wn * 32 + nf * 8 + g) * GB_STRIDE + k0 + t;
                bh[nf][0] = Whs[i0];
                bh[nf][1] = Whs[i0 + 4];
                bl[nf][0] = Wls[i0];
                bl[nf][1] = Wls[i0 + 4];
            }
#pragma unroll
            for (int mf = 0; mf < 4; mf++)
#pragma unroll
                for (int nf = 0; nf < 4; nf++) {
                    mma_bf16(acc[mf][nf], ah[mf], bh[nf][0], bh[nf][1]);
                    mma_bf16(acc[mf][nf], ah[mf], bl[nf][0], bl[nf][1]);
                    mma_bf16(acc[mf][nf], al[mf], bh[nf][0], bh[nf][1]);
                }
        }
        __syncthreads();
    }

    // -------- epilogue (fp32) --------
#pragma unroll
    for (int nf = 0; nf < 4; nf++) {
        const int col = n0 + wn * 32 + nf * 8 + 2 * t;
        const float2 bv = *(const float2*)&bias[col];
#pragma unroll
        for (int mf = 0; mf < 4; mf++) {
            const int r0 = m0 + wm * 64 + mf * 16 + g;
            float2 v0, v1;
            v0.x = acc[mf][nf][0] + bv.x;  v0.y = acc[mf][nf][1] + bv.y;
            v1.x = acc[mf][nf][2] + bv.x;  v1.y = acc[mf][nf][3] + bv.y;
            if (SPLIT) {
                const int h = col >> 6, d = col & 63;
                const int b0 = r0 >> 11, t0 = r0 & 2047;
                *(float2*)&C[(((size_t)b0 * NHEAD + h) * TDIM + t0) * HDIM + d] = v0;
                const int r1 = r0 + 8;
                const int b1 = r1 >> 11, t1 = r1 & 2047;
                *(float2*)&C[(((size_t)b1 * NHEAD + h) * TDIM + t1) * HDIM + d] = v1;
            } else {
                *(float2*)&C[(size_t)r0 * CDIM + col] = v0;
                *(float2*)&C[(size_t)(r0 + 8) * CDIM + col] = v1;
            }
        }
    }
}

// =====================================================================================
// Flash attention (R5 kernel): bf16x2 hi/lo 3-term m16n8k16. BM=128, BN=64, 32 iters.
// Epilogue now writes the output PRE-SPLIT (Ah/Al pair arrays) for the final GEMM.
// =====================================================================================
#define AT_STRIDE 36

__global__ __launch_bounds__(256) void attn_mma(const float* __restrict__ Q,
                                                const float* __restrict__ K,
                                                const float* __restrict__ V,
                                                uint32_t* __restrict__ AHo,
                                                uint32_t* __restrict__ ALo) {
    __shared__ uint32_t KbH[64 * AT_STRIDE];
    __shared__ uint32_t KbL[64 * AT_STRIDE];
    __shared__ uint32_t VtH[64 * AT_STRIDE];
    __shared__ uint32_t VtL[64 * AT_STRIDE];

    const int tid  = threadIdx.x;
    const int lane = tid & 31;
    const int g = lane >> 2, t = lane & 3;
    const int w = tid >> 5;
    const int bh = blockIdx.y;
    const int q0 = blockIdx.x << 7;

    const float* Qg = Q + ((size_t)bh * TDIM + q0) * HDIM;
    const float* Kg = K + (size_t)bh * TDIM * HDIM;
    const float* Vg = V + (size_t)bh * TDIM * HDIM;

    uint32_t qh[4][4], ql[4][4];
    {
        const float sc = 0.125f * 1.4426950408889634f;
        const int r0 = 16 * w + g, r1 = r0 + 8;
#pragma unroll
        for (int ks = 0; ks < 4; ks++) {
            const int c0 = 16 * ks + 2 * t;
            float2 v00 = *(const float2*)&Qg[(size_t)r0 * HDIM + c0];
            float2 v10 = *(const float2*)&Qg[(size_t)r1 * HDIM + c0];
            float2 v01 = *(const float2*)&Qg[(size_t)r0 * HDIM + c0 + 8];
            float2 v11 = *(const float2*)&Qg[(size_t)r1 * HDIM + c0 + 8];
            packsplit(v00.x * sc, v00.y * sc, qh[ks][0], ql[ks][0]);
            packsplit(v10.x * sc, v10.y * sc, qh[ks][1], ql[ks][1]);
            packsplit(v01.x * sc, v01.y * sc, qh[ks][2], ql[ks][2]);
            packsplit(v11.x * sc, v11.y * sc, qh[ks][3], ql[ks][3]);
        }
    }

    const int kc_d  = tid & 31;
    const int kc_k0 = (tid >> 5) << 3;
    const int vc_kp = tid & 31;
    const int vc_d0 = (tid >> 5) << 3;

    float kreg[16], vreg[16];
    auto loadK = [&](int kt) {
        const float* base = Kg + (size_t)((kt << 6) + kc_k0) * HDIM + 2 * kc_d;
#pragma unroll
        for (int j = 0; j < 8; j++) {
            const float2 v = *(const float2*)(base + (size_t)j * HDIM);
            kreg[2 * j] = v.x; kreg[2 * j + 1] = v.y;
        }
    };
    auto loadV = [&](int kt) {
        const float* ba = Vg + (size_t)((kt << 6) + 2 * vc_kp) * HDIM + vc_d0;
#pragma unroll
        for (int q = 0; q < 2; q++) {
            const float4 a = *(const float4*)(ba + (size_t)q * HDIM);
            const float4 b = *(const float4*)(ba + (size_t)q * HDIM + 4);
            vreg[8 * q + 0] = a.x; vreg[8 * q + 1] = a.y; vreg[8 * q + 2] = a.z; vreg[8 * q + 3] = a.w;
            vreg[8 * q + 4] = b.x; vreg[8 * q + 5] = b.y; vreg[8 * q + 6] = b.z; vreg[8 * q + 7] = b.w;
        }
    };

    float o[8][4];
#pragma unroll
    for (int nf = 0; nf < 8; nf++)
#pragma unroll
        for (int q = 0; q < 4; q++) o[nf][q] = 0.0f;

    float m0 = -1e30f, m1 = -1e30f, l0 = 0.0f, l1 = 0.0f;

    loadK(0); loadV(0);

    for (int kt = 0; kt < TDIM / 64; kt++) {
        __syncthreads();
#pragma unroll
        for (int j = 0; j < 8; j++) {
            uint32_t h, l;
            packsplit(kreg[2 * j], kreg[2 * j + 1], h, l);
            KbH[(kc_k0 + j) * AT_STRIDE + kc_d] = h;
            KbL[(kc_k0 + j) * AT_STRIDE + kc_d] = l;
        }
#pragma unroll
        for (int j = 0; j < 8; j++) {
            uint32_t h, l;
            packsplit(vreg[j], vreg[8 + j], h, l);
            VtH[(vc_d0 + j) * AT_STRIDE + vc_kp] = h;
            VtL[(vc_d0 + j) * AT_STRIDE + vc_kp] = l;
        }
        if (kt + 1 < TDIM / 64) { loadK(kt + 1); loadV(kt + 1); }
        __syncthreads();

        float s[8][4];
#pragma unroll
        for (int nf = 0; nf < 8; nf++)
#pragma unroll
            for (int q = 0; q < 4; q++) s[nf][q] = 0.0f;

#pragma unroll
        for (int ks = 0; ks < 4; ks++) {
#pragma unroll
            for (int nf = 0; nf < 8; nf++) {
                const int i0 = (8 * nf + g) * AT_STRIDE + 8 * ks + t;
                const uint32_t kh0 = KbH[i0], kh1 = KbH[i0 + 4];
                const uint32_t kl0 = KbL[i0], kl1 = KbL[i0 + 4];
                mma_bf16(s[nf], qh[ks], kh0, kh1);
                mma_bf16(s[nf], qh[ks], kl0, kl1);
                mma_bf16(s[nf], ql[ks], kh0, kh1);
            }
        }

        float mx0 = -1e30f, mx1 = -1e30f;
#pragma unroll
        for (int nf = 0; nf < 8; nf++) {
            mx0 = fmaxf(mx0, fmaxf(s[nf][0], s[nf][1]));
            mx1 = fmaxf(mx1, fmaxf(s[nf][2], s[nf][3]));
        }
        mx0 = fmaxf(mx0, __shfl_xor_sync(0xffffffffu, mx0, 1));
        mx0 = fmaxf(mx0, __shfl_xor_sync(0xffffffffu, mx0, 2));
        mx1 = fmaxf(mx1, __shfl_xor_sync(0xffffffffu, mx1, 1));
        mx1 = fmaxf(mx1, __shfl_xor_sync(0xffffffffu, mx1, 2));

        const float mn0 = fmaxf(m0, mx0), mn1 = fmaxf(m1, mx1);
        const float a0 = exp2f(m0 - mn0), a1 = exp2f(m1 - mn1);
        m0 = mn0; m1 = mn1;

        float sum0 = 0.0f, sum1 = 0.0f;
#pragma unroll
        for (int nf = 0; nf < 8; nf++) {
            s[nf][0] = exp2f(s[nf][0] - m0);
            s[nf][1] = exp2f(s[nf][1] - m0);
            s[nf][2] = exp2f(s[nf][2] - m1);
            s[nf][3] = exp2f(s[nf][3] - m1);
            sum0 += s[nf][0] + s[nf][1];
            sum1 += s[nf][2] + s[nf][3];
        }
        sum0 += __shfl_xor_sync(0xffffffffu, sum0, 1);
        sum0 += __shfl_xor_sync(0xffffffffu, sum0, 2);
        sum1 += __shfl_xor_sync(0xffffffffu, sum1, 1);
        sum1 += __shfl_xor_sync(0xffffffffu, sum1, 2);
        l0 = l0 * a0 + sum0;
        l1 = l1 * a1 + sum1;

#pragma unroll
        for (int nf = 0; nf < 8; nf++) {
            o[nf][0] *= a0; o[nf][1] *= a0;
            o[nf][2] *= a1; o[nf][3] *= a1;
        }

        uint32_t pha[8], phb[8], pla[8], plb[8];
#pragma unroll
        for (int nf = 0; nf < 8; nf++) {
            packsplit(s[nf][0], s[nf][1], pha[nf], pla[nf]);
            packsplit(s[nf][2], s[nf][3], phb[nf], plb[nf]);
        }

#pragma unroll
        for (int ks = 0; ks < 4; ks++) {
            const uint32_t ah[4] = {pha[2 * ks], phb[2 * ks], pha[2 * ks + 1], phb[2 * ks + 1]};
            const uint32_t al[4] = {pla[2 * ks], plb[2 * ks], pla[2 * ks + 1], plb[2 * ks + 1]};
#pragma unroll
            for (int nf = 0; nf < 8; nf++) {
                const int i0 = (8 * nf + g) * AT_STRIDE + 8 * ks + t;
                const uint32_t vh0 = VtH[i0], vh1 = VtH[i0 + 4];
                const uint32_t vl0 = VtL[i0], vl1 = VtL[i0 + 4];
                mma_bf16(o[nf], ah, vh0, vh1);
                mma_bf16(o[nf], ah, vl0, vl1);
                mma_bf16(o[nf], al, vh0, vh1);
            }
        }
    }

    // ---- epilogue: normalize + pre-split write into Ah/Al pair arrays ----
    const float inv0 = 1.0f / l0, inv1 = 1.0f / l1;
    const int b = bh >> 4, h = bh & 15;
    const int r0 = q0 + 16 * w + g, r1 = r0 + 8;
    const size_t n0r = (size_t)(b * TDIM + r0) * KPAIRS + h * (HDIM / 2);
    const size_t n1r = (size_t)(b * TDIM + r1) * KPAIRS + h * (HDIM / 2);
#pragma unroll
    for (int nf = 0; nf < 8; nf++) {
        uint32_t h0, l0u, h1, l1u;
        packsplit(o[nf][0] * inv0, o[nf][1] * inv0, h0, l0u);
        packsplit(o[nf][2] * inv1, o[nf][3] * inv1, h1, l1u);
        const int cp = 4 * nf + t;          // column pair within head
        AHo[n0r + cp] = h0;  ALo[n0r + cp] = l0u;
        AHo[n1r + cp] = h1;  ALo[n1r + cp] = l1u;
    }
}

// =====================================================================================
extern "C" void kernel_launch(void* const* d_in, const int* in_sizes, int n_in,
                              void* d_out, int out_size) {
    const float* x  = (const float*)d_in[0];
    const float* Wq = (const float*)d_in[1];
    const float* bq = (const float*)d_in[2];
    const float* Wk = (const float*)d_in[3];
    const float* bk = (const float*)d_in[4];
    const float* Wv = (const float*)d_in[5];
    const float* bv = (const float*)d_in[6];
    const float* Wp = (const float*)d_in[7];
    const float* bp = (const float*)d_in[8];
    float* out = (float*)d_out;

    float *Qp, *Kp, *Vp;
    uint32_t *XH, *XL, *WH, *WL, *AH, *AL;
    cudaGetSymbolAddress((void**)&Qp, g_Q);
    cudaGetSymbolAddress((void**)&Kp, g_K);
    cudaGetSymbolAddress((void**)&Vp, g_V);
    cudaGetSymbolAddress((void**)&XH, g_XH);
    cudaGetSymbolAddress((void**)&XL, g_XL);
    cudaGetSymbolAddress((void**)&WH, g_WH);
    cudaGetSymbolAddress((void**)&WL, g_WL);
    cudaGetSymbolAddress((void**)&AH, g_AH);
    cudaGetSymbolAddress((void**)&AL, g_AL);

    const size_t WPAIR = (size_t)CDIM * KPAIRS;   // 524288
    const int NPX = NTOK * KPAIRS;                // 4194304

    // pre-split operands
    splitpack<<<(NPX + 255) / 256, 256>>>(x, XH, XL, NPX);
    splitpack<<<((int)WPAIR + 255) / 256, 256>>>(Wq, WH + 0 * WPAIR, WL + 0 * WPAIR, (int)WPAIR);
    splitpack<<<((int)WPAIR + 255) / 256, 256>>>(Wk, WH + 1 * WPAIR, WL + 1 * WPAIR, (int)WPAIR);
    splitpack<<<((int)WPAIR + 255) / 256, 256>>>(Wv, WH + 2 * WPAIR, WL + 2 * WPAIR, (int)WPAIR);
    splitpack<<<((int)WPAIR + 255) / 256, 256>>>(Wp, WH + 3 * WPAIR, WL + 3 * WPAIR, (int)WPAIR);

    cudaFuncSetAttribute(gemm_bf16<1>, cudaFuncAttributeMaxDynamicSharedMemorySize, GB_SMEM);
    cudaFuncSetAttribute(gemm_bf16<0>, cudaFuncAttributeMaxDynamicSharedMemorySize, GB_SMEM);

    const dim3 gg(CDIM / 128, NTOK / 128);   // (8, 64)

    gemm_bf16<1><<<gg, 256, GB_SMEM>>>(XH, XL, WH + 0 * WPAIR, WL + 0 * WPAIR, bq, Qp);
    gemm_bf16<1><<<gg, 256, GB_SMEM>>>(XH, XL, WH + 1 * WPAIR, WL + 1 * WPAIR, bk, Kp);
    gemm_bf16<1><<<gg, 256, GB_SMEM>>>(XH, XL, WH + 2 * WPAIR, WL + 2 * WPAIR, bv, Vp);

    const dim3 ga(TDIM / 128, BDIM * NHEAD);  // (16, 64)
    attn_mma<<<ga, 256>>>(Qp, Kp, Vp, AH, AL);

    gemm_bf16<0><<<gg, 256, GB_SMEM>>>(AH, AL, WH + 3 * WPAIR, WL + 3 * WPAIR, bp, out);
}